// round 15
// baseline (speedup 1.0000x reference)
#include <cuda_runtime.h>
#include <cstdint>

// out = chem @ (Wout @ Wv)^T + (Wout @ bv + bout)   (softmax over singleton == 1)
//
// Tensor-core path (R13/R14): folded 16x16 matvec as mma.sync.m16n8k8.tf32,
// 3-term compensated (x_hi*M_hi + x_hi*M_lo + x_lo*M_hi) -> fp32-grade
// accuracy. A-fragments loaded DIRECTLY from gmem (8 LDG.32/warp-tile),
// D-fragments stored directly (4 STG.64). Persistent grid, 3 CTAs/SM.
// NEW vs R14: FOUR-buffer per-warp pipeline (3 tiles ahead -> 72 KB/SM in
// flight), using the 8 registers left under the 84-reg/3-CTA cap.

#define DIMN 16
#define NCTA 444          // 3 per SM x 148

typedef unsigned int u32;

__device__ __forceinline__ void mma_tf32(float& d0, float& d1, float& d2, float& d3,
                                         u32 a0, u32 a1, u32 a2, u32 a3,
                                         u32 b0, u32 b1) {
    asm("mma.sync.aligned.m16n8k8.row.col.f32.tf32.tf32.f32 "
        "{%0,%1,%2,%3}, {%4,%5,%6,%7}, {%8,%9}, {%0,%1,%2,%3};"
        : "+f"(d0), "+f"(d1), "+f"(d2), "+f"(d3)
        : "r"(a0), "r"(a1), "r"(a2), "r"(a3), "r"(b0), "r"(b1));
}

// Tile = 16 consecutive rows = 256 floats = 1 KB, processed by one warp.
// Lane (grp = lane>>2, tid = lane&3) loads x[grp + 8rr][tid + 4cc], rr<2, cc<4.
template <bool GUARD>
__device__ __forceinline__ void load_tile(float v[8], const float* __restrict__ gin,
                                          int lbase, bool live, int total) {
    if (!live) return;
#pragma unroll
    for (int j = 0; j < 8; j++) {
        int e = lbase + (j >> 2) * 128 + (j & 3) * 4;
        if (GUARD) v[j] = (e < total) ? gin[e] : 0.f;
        else       v[j] = gin[e];
    }
}

template <bool GUARD>
__device__ __forceinline__ void proc_tile(const float v[8], float* __restrict__ gout,
                                          int T, int grp, int tid, int total,
                                          const u32 bHi[2][2][2],
                                          const u32 bLo[2][2][2],
                                          const float cb[2][2]) {
    // Split x into tf32-exact hi + residual lo.
    u32 ah[8], al[8];
#pragma unroll
    for (int j = 0; j < 8; j++) {
        u32 u = __float_as_uint(v[j]) & 0xffffe000u;
        ah[j] = u;
        al[j] = __float_as_uint(v[j] - __uint_as_float(u));
    }
    int sbase = T * 256 + grp * 16 + 2 * tid;
#pragma unroll
    for (int nh = 0; nh < 2; nh++) {
        float d0 = cb[nh][0], d1 = cb[nh][1], d2 = d0, d3 = d1;  // bias seed
#pragma unroll
        for (int kk = 0; kk < 2; kk++) {
            u32 A0 = ah[2 * kk], A1 = ah[4 + 2 * kk];
            u32 A2 = ah[2 * kk + 1], A3 = ah[4 + 2 * kk + 1];
            u32 L0 = al[2 * kk], L1 = al[4 + 2 * kk];
            u32 L2 = al[2 * kk + 1], L3 = al[4 + 2 * kk + 1];
            mma_tf32(d0, d1, d2, d3, A0, A1, A2, A3, bHi[kk][nh][0], bHi[kk][nh][1]);
            mma_tf32(d0, d1, d2, d3, A0, A1, A2, A3, bLo[kk][nh][0], bLo[kk][nh][1]);
            mma_tf32(d0, d1, d2, d3, L0, L1, L2, L3, bHi[kk][nh][0], bHi[kk][nh][1]);
        }
        // D-frag: (grp, 8nh+2tid..+1) and (grp+8, same cols) -> two STG.64.
        int e0 = sbase + 8 * nh;
        int e1 = e0 + 128;
        if (!GUARD || e0 < total) __stcs((float2*)&gout[e0], make_float2(d0, d1));
        if (!GUARD || e1 < total) __stcs((float2*)&gout[e1], make_float2(d2, d3));
    }
}

template <bool GUARD>
__global__ __launch_bounds__(256, 3)
void xattn_kernel(const float* __restrict__ gin, float* __restrict__ gout,
                  const float* __restrict__ w_in, const float* __restrict__ b_in,
                  const float* __restrict__ w_out, const float* __restrict__ b_out,
                  int total, int ntiles) {
    __shared__ float sM[DIMN * DIMN];   // sM[j*16+i] = (Wout @ Wv)[j][i]
    __shared__ float sC[DIMN];          // c = Wout @ bv + bout

    int t = threadIdx.x;
    {   // per-CTA weight folding
        int j = t >> 4, i = t & 15;
        float m = 0.f;
#pragma unroll
        for (int k = 0; k < DIMN; k++)
            m += w_out[j * DIMN + k] * w_in[(2 * DIMN + k) * DIMN + i];  // Wv rows 32..47
        sM[j * DIMN + i] = m;
        if (i == 0) {
            float c = b_out[j];
#pragma unroll
            for (int k = 0; k < DIMN; k++)
                c += w_out[j * DIMN + k] * b_in[2 * DIMN + k];
            sC[j] = c;
        }
    }
    __syncthreads();

    const int lane = t & 31, grp = lane >> 2, tid = lane & 3;

    // B-fragments: b_h = M[8nh+grp][8kk+tid+4h], split hi/lo.
    u32 bHi[2][2][2], bLo[2][2][2];
#pragma unroll
    for (int kk = 0; kk < 2; kk++)
#pragma unroll
        for (int nh = 0; nh < 2; nh++)
#pragma unroll
            for (int h = 0; h < 2; h++) {
                float m = sM[(8 * nh + grp) * DIMN + 8 * kk + tid + 4 * h];
                u32 u = __float_as_uint(m) & 0xffffe000u;
                bHi[kk][nh][h] = u;
                bLo[kk][nh][h] = __float_as_uint(m - __uint_as_float(u));
            }
    float cb[2][2];
#pragma unroll
    for (int nh = 0; nh < 2; nh++) {
        cb[nh][0] = sC[8 * nh + 2 * tid];
        cb[nh][1] = sC[8 * nh + 2 * tid + 1];
    }

    const int W = gridDim.x << 3;              // total warps (persistent)
    int T = (blockIdx.x << 3) + (t >> 5);
    if (T >= ntiles) return;
    const int lofs = grp * 16 + tid;

    float v0[8], v1[8], v2[8], v3[8];

    // Prologue: 3 tiles in flight before first compute.
    load_tile<GUARD>(v0, gin, T * 256 + lofs, true, total);
    load_tile<GUARD>(v1, gin, (T + W) * 256 + lofs, T + W < ntiles, total);
    load_tile<GUARD>(v2, gin, (T + 2 * W) * 256 + lofs, T + 2 * W < ntiles, total);

    while (true) {
        load_tile<GUARD>(v3, gin, (T + 3 * W) * 256 + lofs, T + 3 * W < ntiles, total);
        proc_tile<GUARD>(v0, gout, T, grp, tid, total, bHi, bLo, cb);
        T += W; if (T >= ntiles) return;

        load_tile<GUARD>(v0, gin, (T + 3 * W) * 256 + lofs, T + 3 * W < ntiles, total);
        proc_tile<GUARD>(v1, gout, T, grp, tid, total, bHi, bLo, cb);
        T += W; if (T >= ntiles) return;

        load_tile<GUARD>(v1, gin, (T + 3 * W) * 256 + lofs, T + 3 * W < ntiles, total);
        proc_tile<GUARD>(v2, gout, T, grp, tid, total, bHi, bLo, cb);
        T += W; if (T >= ntiles) return;

        load_tile<GUARD>(v2, gin, (T + 3 * W) * 256 + lofs, T + 3 * W < ntiles, total);
        proc_tile<GUARD>(v3, gout, T, grp, tid, total, bHi, bLo, cb);
        T += W; if (T >= ntiles) return;
    }
}

extern "C" void kernel_launch(void* const* d_in, const int* in_sizes, int n_in,
                              void* d_out, int out_size) {
    // inputs: 0 fp_16 (unused), 1 chem_16, 2 in_proj_weight, 3 in_proj_bias,
    //         4 out_proj_weight, 5 out_proj_bias
    const float* chem  = (const float*)d_in[1];
    const float* w_in  = (const float*)d_in[2];
    const float* b_in  = (const float*)d_in[3];
    const float* w_out = (const float*)d_in[4];
    const float* b_out = (const float*)d_in[5];

    int total  = in_sizes[1];                  // floats (rows * 16)
    int ntiles = (total + 255) / 256;
    int blocks = (ntiles + 7) / 8;
    if (blocks > NCTA) blocks = NCTA;

    if (total % 256 == 0) {
        xattn_kernel<false><<<blocks, 256>>>((const float*)chem, (float*)d_out,
                                             w_in, b_in, w_out, b_out,
                                             total, ntiles);
    } else {
        xattn_kernel<true><<<blocks, 256>>>((const float*)chem, (float*)d_out,
                                            w_in, b_in, w_out, b_out,
                                            total, ntiles);
    }
}